// round 4
// baseline (speedup 1.0000x reference)
#include <cuda_runtime.h>

#define NUM_INPUT  700
#define NUM_HIDDEN 256
#define NUM_OUTPUT 20
#define WIN        50
#define BATCH      512
#define THRESH     0.3f
#define ALPHA      0.8f

#define M_ROWS (BATCH * WIN)   // 25600

typedef unsigned long long ull;

// ---------------- f32x2 helpers ----------------
__device__ __forceinline__ ull pack2(float x, float y) {
    ull r; asm("mov.b64 %0, {%1, %2};" : "=l"(r) : "f"(x), "f"(y)); return r;
}
__device__ __forceinline__ void unpack2(ull v, float& x, float& y) {
    asm("mov.b64 {%0, %1}, %2;" : "=f"(x), "=f"(y) : "l"(v));
}
__device__ __forceinline__ void ffma2(ull& d, ull a, ull b) {   // d = a*b + d
    asm("fma.rn.f32x2 %0, %1, %2, %0;" : "+l"(d) : "l"(a), "l"(b));
}
__device__ __forceinline__ ull fma2n(ull a, ull b, ull c) {     // a*b + c
    ull d; asm("fma.rn.f32x2 %0, %1, %2, %3;" : "=l"(d) : "l"(a), "l"(b), "l"(c)); return d;
}
__device__ __forceinline__ ull add2(ull a, ull b) {
    ull d; asm("add.rn.f32x2 %0, %1, %2;" : "=l"(d) : "l"(a), "l"(b)); return d;
}
__device__ __forceinline__ ulonglong2 ldg128(const float* p) {
    ulonglong2 v;
    asm("ld.global.nc.v2.u64 {%0, %1}, [%2];" : "=l"(v.x), "=l"(v.y) : "l"(p));
    return v;
}

// ---------------- device scratch ----------------
__device__ float g_WcT[3 * NUM_INPUT * NUM_HIDDEN];
__device__ float g_WfT[2 * NUM_HIDDEN * NUM_HIDDEN];
__device__ float g_WrT[2 * NUM_HIDDEN * NUM_HIDDEN];
__device__ float g_WoT[NUM_HIDDEN * NUM_OUTPUT];
__device__ float g_cvec[NUM_HIDDEN];
__device__ float g_ff0[M_ROWS * NUM_HIDDEN];

// ---------------- prep kernels ----------------
__global__ void prep_transpose(const float* __restrict__ Wf,
                               const float* __restrict__ Wr,
                               const float* __restrict__ Wo) {
    int idx = blockIdx.x * 256 + threadIdx.x;
    if (idx < 2 * 256 * 256) {
        int h = idx & 255;
        int k = (idx >> 8) & 255;
        int l = idx >> 16;
        g_WfT[(l * 256 + k) * 256 + h] = Wf[(l * 256 + h) * 256 + k];
        g_WrT[(l * 256 + k) * 256 + h] = Wr[(l * 256 + h) * 256 + k];
    }
    if (idx < 256 * 20) {
        int o = idx % 20;
        int k = idx / 20;
        g_WoT[k * 20 + o] = Wo[o * 256 + k];
    }
}

__global__ void prep_wc(const float* __restrict__ Wd) {
    int ik = blockIdx.x;
    int i = ik / NUM_INPUT;
    int k = ik % NUM_INPUT;
    int h = threadIdx.x;
    float s = 0.f;
#pragma unroll 8
    for (int j = 0; j < 256; j++) {
        s += g_WfT[j * 256 + h] * __ldg(&Wd[(i * 256 + j) * NUM_INPUT + k]);
    }
    g_WcT[(i * NUM_INPUT + k) * 256 + h] = s;
}

__global__ void prep_cvec(const float* __restrict__ bd, const float* __restrict__ bf) {
    int h = threadIdx.x;
    float s = bf[h];
#pragma unroll 8
    for (int j = 0; j < 256; j++) {
        float bsum = bd[j] + bd[256 + j] + bd[512 + j];
        s += bsum * g_WfT[j * 256 + h];
    }
    g_cvec[h] = s;
}

// ---------------- ff0 GEMM, double-buffered, dup-B ----------------
#define GA_BM 128
#define GA_BN 64
#define GA_BK 16
#define NTILES (3 * 44)     // 3 delay segs x ceil(700/16)

__global__ __launch_bounds__(256) void gemm_ff0(const float* __restrict__ x) {
    __shared__ __align__(16) float As[2][GA_BK][GA_BM + 4];
    __shared__ __align__(16) float Bs[2][GA_BK][2 * GA_BN + 4];

    const int tid = threadIdx.x;
    const int rowBase = blockIdx.y * GA_BM;
    const int colBase = blockIdx.x * GA_BN;
    const int tx = tid & 15;
    const int ty = tid >> 4;

    const int mm = tid >> 2;            // 0..63
    const int kq = (tid & 3) * 4;       // 0,4,8,12
    const int kkB = tid >> 4;           // 0..15
    const int hhB = (tid & 15) * 4;

    const int gr = rowBase + mm;
    const int gb = gr / WIN, gt = gr - (gr / WIN) * WIN;
    const int gr2 = gr + 64;
    const int gb2 = gr2 / WIN, gt2 = gr2 - (gr2 / WIN) * WIN;

    ull acc[4][4];
#pragma unroll
    for (int p = 0; p < 4; p++)
#pragma unroll
        for (int j = 0; j < 4; j++) acc[p][j] = 0ull;

    float4 ra0, ra1, rb;

#define GLOAD(IT) {                                                              \
        int seg = (IT) / 44;                                                     \
        int kb = ((IT) - seg * 44) * GA_BK;                                      \
        int d = seg * 16;                                                        \
        int kg = kb + kq;                                                        \
        bool kv = (kg < NUM_INPUT);                                              \
        int ts1 = gt - d;                                                        \
        ra0 = make_float4(0.f, 0.f, 0.f, 0.f);                                   \
        if (kv && ts1 >= 0)                                                      \
            ra0 = __ldg((const float4*)(x + ((size_t)gb * WIN + ts1) * NUM_INPUT + kg)); \
        int ts2 = gt2 - d;                                                       \
        ra1 = make_float4(0.f, 0.f, 0.f, 0.f);                                   \
        if (kv && ts2 >= 0)                                                      \
            ra1 = __ldg((const float4*)(x + ((size_t)gb2 * WIN + ts2) * NUM_INPUT + kg)); \
        int kg2 = kb + kkB;                                                      \
        rb = make_float4(0.f, 0.f, 0.f, 0.f);                                    \
        if (kg2 < NUM_INPUT)                                                     \
            rb = __ldg((const float4*)(g_WcT + (size_t)seg * NUM_INPUT * 256 + (size_t)kg2 * 256 + colBase + hhB)); \
    }

#define GSTORE(BUF) {                                                            \
        As[BUF][kq + 0][mm] = ra0.x;  As[BUF][kq + 1][mm] = ra0.y;               \
        As[BUF][kq + 2][mm] = ra0.z;  As[BUF][kq + 3][mm] = ra0.w;               \
        As[BUF][kq + 0][mm + 64] = ra1.x;  As[BUF][kq + 1][mm + 64] = ra1.y;     \
        As[BUF][kq + 2][mm + 64] = ra1.z;  As[BUF][kq + 3][mm + 64] = ra1.w;     \
        *(float4*)&Bs[BUF][kkB][hhB * 2]     = make_float4(rb.x, rb.x, rb.y, rb.y); \
        *(float4*)&Bs[BUF][kkB][hhB * 2 + 4] = make_float4(rb.z, rb.z, rb.w, rb.w); \
    }

    GLOAD(0);
    GSTORE(0);
    __syncthreads();

    for (int it = 0; it < NTILES; it++) {
        if (it + 1 < NTILES) GLOAD(it + 1);
        const int buf = it & 1;
#pragma unroll
        for (int kk = 0; kk < GA_BK; kk++) {
            const ulonglong2* ap = (const ulonglong2*)&As[buf][kk][ty * 8];
            ulonglong2 a01 = ap[0], a23 = ap[1];
            const ulonglong2* bp = (const ulonglong2*)&Bs[buf][kk][tx * 8];
            ulonglong2 b01 = bp[0], b23 = bp[1];
            ull av[4] = {a01.x, a01.y, a23.x, a23.y};
            ull bv[4] = {b01.x, b01.y, b23.x, b23.y};
#pragma unroll
            for (int p = 0; p < 4; p++)
#pragma unroll
                for (int j = 0; j < 4; j++) ffma2(acc[p][j], av[p], bv[j]);
        }
        if (it + 1 < NTILES) GSTORE((it + 1) & 1);
        __syncthreads();
    }

#pragma unroll
    for (int p = 0; p < 4; p++) {
#pragma unroll
        for (int j = 0; j < 4; j++) {
            float v0, v1;
            unpack2(acc[p][j], v0, v1);
            int c = colBase + tx * 4 + j;
            int r0 = rowBase + ty * 8 + 2 * p;
            g_ff0[(size_t)r0 * 256 + c] = v0 + g_cvec[c];
            g_ff0[(size_t)(r0 + 1) * 256 + c] = v1 + g_cvec[c];
        }
    }
#undef GLOAD
#undef GSTORE
}

// ---------------- recurrent scan ----------------
// 64 blocks x 512 threads. Thread = (ks = tid>>6 in 0..7, hq = tid&63).
// Thread accumulates rows 0..7 x h-quad (4hq..4hq+3) over k in [ks*32, ks*32+32).
// Spikes stored PRE-DUPLICATED: sp[h][2r],[2r+1] = s  (stride 20 floats per h).
// Reduction via transposed partial buffer: slot [(r*8+ks)*64+hq] (conflict-free).
#define OFFP    0                      // partials: 8*8*64 ulonglong2 = 16384 floats (64KB)
#define OFFS0   16384                  // sp0 dup: 256*20 = 5120
#define OFFS1   (OFFS0 + 5120)         // 21504
#define OFFWOT  (OFFS1 + 5120)         // 26624
#define OFFOSM  (OFFWOT + 5120)        // 31744
#define OFFOTMP (OFFOSM + 160)         // 31904
#define OFFOSUM (OFFOTMP + 160)        // 32064
#define SCAN_FLOATS (OFFOSUM + 8)      // 32072 floats = 128288 bytes

__device__ __forceinline__ void accum_quad(ull acc[8][2], const float* __restrict__ wg,
                                           int hq4, const float* __restrict__ sp, int kbeg) {
#pragma unroll 4
    for (int k = kbeg; k < kbeg + 32; k++) {
        ulonglong2 w = ldg128(wg + (size_t)k * 256 + hq4);
        const ulonglong2* sq = (const ulonglong2*)(sp + k * 20);
        ulonglong2 s01 = sq[0], s23 = sq[1], s45 = sq[2], s67 = sq[3];
        ffma2(acc[0][0], w.x, s01.x); ffma2(acc[0][1], w.y, s01.x);
        ffma2(acc[1][0], w.x, s01.y); ffma2(acc[1][1], w.y, s01.y);
        ffma2(acc[2][0], w.x, s23.x); ffma2(acc[2][1], w.y, s23.x);
        ffma2(acc[3][0], w.x, s23.y); ffma2(acc[3][1], w.y, s23.y);
        ffma2(acc[4][0], w.x, s45.x); ffma2(acc[4][1], w.y, s45.x);
        ffma2(acc[5][0], w.x, s45.y); ffma2(acc[5][1], w.y, s45.y);
        ffma2(acc[6][0], w.x, s67.x); ffma2(acc[6][1], w.y, s67.x);
        ffma2(acc[7][0], w.x, s67.y); ffma2(acc[7][1], w.y, s67.y);
    }
}

__global__ __launch_bounds__(512) void scan_kernel(const float* __restrict__ bf,
                                                   const float* __restrict__ bo,
                                                   float* __restrict__ out) {
    extern __shared__ float sm[];
    ulonglong2* partq = (ulonglong2*)(sm + OFFP);
    float* sp0  = sm + OFFS0;
    float* sp1  = sm + OFFS1;
    float* wot  = sm + OFFWOT;
    float* opart = sm + OFFP;          // alias (safe: separated by syncs)
    float* osm  = sm + OFFOSM;
    float* otmp = sm + OFFOTMP;
    float* osum = sm + OFFOSUM;

    const int tid = threadIdx.x;
    const int ks = tid >> 6;           // 0..7  (k-split AND owned row)
    const int hq = tid & 63;           // h-quad index
    const int hq4 = hq * 4;
    const int b0 = blockIdx.x * 8;

    for (int i = tid; i < 256 * 20; i += 512) wot[i] = g_WoT[i];
    for (int i = tid; i < 5120; i += 512) { sp0[i] = 0.f; sp1[i] = 0.f; }
    __syncthreads();

    // membrane state for (row ks, h quad)
    ull m0a = 0, m0b = 0, m1a = 0, m1b = 0;
    const ull alpha2 = pack2(ALPHA, ALPHA);
    ull df0a = alpha2, df0b = alpha2, df1a = alpha2, df1b = alpha2;

    float4 bfq = __ldg((const float4*)(bf + 256 + hq4));
    const ull bf1a = pack2(bfq.x, bfq.y);
    const ull bf1b = pack2(bfq.z, bfq.w);

    // output roles
    const int seg = (tid >= 160 && tid < 320) ? 1 : 0;
    const int rr = (tid < 160) ? tid : (tid < 320 ? tid - 160 : 0);
    const int orow = rr / 20, ocol = rr - orow * 20;
    const int okbeg = seg * 128;
    const float bov = (tid < 160) ? __ldg(bo + ocol) : 0.f;
    float o_mem = 0.f, o_dfac = ALPHA, o_sumv = 0.f, o_mot = 0.f;

    const float* __restrict__ wr0g = g_WrT;
    const float* __restrict__ wf1g = g_WfT + 65536;
    const float* __restrict__ wr1g = g_WrT + 65536;

    const int kbeg = ks * 32;

    for (int t = 0; t < WIN; t++) {
        // prefetch ff0 for (row b0+ks, t, hq4..hq4+3)
        float4 ffv = __ldg((const float4*)(g_ff0 + ((size_t)(b0 + ks) * WIN + t) * 256 + hq4));

        // ---- stage 1: layer0 partial accumulation ----
        ull acc[8][2];
#pragma unroll
        for (int r = 0; r < 8; r++) { acc[r][0] = 0ull; acc[r][1] = 0ull; }
        accum_quad(acc, wr0g, hq4, sp0, kbeg);
#pragma unroll
        for (int r = 0; r < 8; r++)
            partq[(r * 8 + ks) * 64 + hq] = make_ulonglong2(acc[r][0], acc[r][1]);
        __syncthreads();                                        // S1

        // ---- stage 2: reduce, membrane0, spikes ----
        {
            ull r0 = 0ull, r1 = 0ull;
#pragma unroll
            for (int j = 0; j < 8; j++) {
                ulonglong2 p = partq[(ks * 8 + j) * 64 + hq];
                r0 = add2(r0, p.x); r1 = add2(r1, p.y);
            }
            r0 = add2(r0, pack2(ffv.x, ffv.y));
            r1 = add2(r1, pack2(ffv.z, ffv.w));
            m0a = fma2n(m0a, df0a, r0);
            m0b = fma2n(m0b, df0b, r1);
            float mx, my, mz, mw;
            unpack2(m0a, mx, my); unpack2(m0b, mz, mw);
            float sx = (mx - THRESH > 0.f) ? 1.f : 0.f;
            float sy = (my - THRESH > 0.f) ? 1.f : 0.f;
            float sz = (mz - THRESH > 0.f) ? 1.f : 0.f;
            float sw = (mw - THRESH > 0.f) ? 1.f : 0.f;
            df0a = pack2(ALPHA * (1.f - sx), ALPHA * (1.f - sy));
            df0b = pack2(ALPHA * (1.f - sz), ALPHA * (1.f - sw));
            *(float2*)(sp0 + (hq4 + 0) * 20 + 2 * ks) = make_float2(sx, sx);
            *(float2*)(sp0 + (hq4 + 1) * 20 + 2 * ks) = make_float2(sy, sy);
            *(float2*)(sp0 + (hq4 + 2) * 20 + 2 * ks) = make_float2(sz, sz);
            *(float2*)(sp0 + (hq4 + 3) * 20 + 2 * ks) = make_float2(sw, sw);
        }
        __syncthreads();                                        // S2

        // ---- stage 3: layer1 partial accumulation (ff from sp0 new, rec from sp1 old) ----
#pragma unroll
        for (int r = 0; r < 8; r++) { acc[r][0] = 0ull; acc[r][1] = 0ull; }
        accum_quad(acc, wf1g, hq4, sp0, kbeg);
        accum_quad(acc, wr1g, hq4, sp1, kbeg);
#pragma unroll
        for (int r = 0; r < 8; r++)
            partq[(r * 8 + ks) * 64 + hq] = make_ulonglong2(acc[r][0], acc[r][1]);
        __syncthreads();                                        // S3

        // ---- stage 4: reduce, membrane1, spikes ----
        {
            ull r0 = 0ull, r1 = 0ull;
#pragma unroll
            for (int j = 0; j < 8; j++) {
                ulonglong2 p = partq[(ks * 8 + j) * 64 + hq];
                r0 = add2(r0, p.x); r1 = add2(r1, p.y);
            }
            r0 = add2(r0, bf1a);
            r1 = add2(r1, bf1b);
            m1a = fma2n(m1a, df1a, r0);
            m1b = fma2n(m1b, df1b, r1);
            float mx, my, mz, mw;
            unpack2(m1a, mx, my); unpack2(m1b, mz, mw);
            float sx = (mx - THRESH > 0.f) ? 1.f : 0.f;
            float sy = (my - THRESH > 0.f) ? 1.f : 0.f;
            float sz = (mz - THRESH > 0.f) ? 1.f : 0.f;
            float sw = (mw - THRESH > 0.f) ? 1.f : 0.f;
            df1a = pack2(ALPHA * (1.f - sx), ALPHA * (1.f - sy));
            df1b = pack2(ALPHA * (1.f - sz), ALPHA * (1.f - sw));
            *(float2*)(sp1 + (hq4 + 0) * 20 + 2 * ks) = make_float2(sx, sx);
            *(float2*)(sp1 + (hq4 + 1) * 20 + 2 * ks) = make_float2(sy, sy);
            *(float2*)(sp1 + (hq4 + 2) * 20 + 2 * ks) = make_float2(sz, sz);
            *(float2*)(sp1 + (hq4 + 3) * 20 + 2 * ks) = make_float2(sw, sw);
        }
        __syncthreads();                                        // S4

        // ---- stage 5: output partials ----
        if (tid < 320) {
            float oa = 0.f;
#pragma unroll 8
            for (int k = okbeg; k < okbeg + 128; k++) {
                oa += sp1[k * 20 + 2 * orow] * wot[k * 20 + ocol];
            }
            opart[tid] = oa;
        }
        __syncthreads();                                        // S5

        // ---- stage 6: output membrane ----
        if (tid < 160) {
            float oa = opart[tid] + opart[tid + 160] + bov;
            o_mem = o_mem * o_dfac + oa;
            float os = (o_mem - THRESH > 0.f) ? 1.f : 0.f;
            o_dfac = ALPHA * (1.f - os);
            o_sumv += os;
            osm[tid] = o_mem;
        }
        __syncthreads();                                        // S6

        // ---- stage 7: per-row softmax (8 rows, serial 20-wide) ----
        if (tid < 8) {
            float mx = -1e30f;
#pragma unroll
            for (int o = 0; o < 20; o++) mx = fmaxf(mx, osm[tid * 20 + o]);
            float s = 0.f;
#pragma unroll
            for (int o = 0; o < 20; o++) {
                float e = expf(osm[tid * 20 + o] - mx);
                otmp[tid * 20 + o] = e;
                s += e;
            }
            osum[tid] = s;
        }
        __syncthreads();                                        // S7

        // ---- stage 8: accumulate softmax prob ----
        if (tid < 160) {
            o_mot += otmp[tid] / osum[orow];
        }
        // no sync needed: next step's S1 only touches partq after long compute,
        // and otmp/osum are rewritten only after S6/S7 of the next step.
        __syncthreads();                                        // keep uniform safety
    }

    if (tid < 160) {
        int b = b0 + orow;
        out[b * 20 + ocol] = o_sumv / (float)WIN;
        out[BATCH * 20 + b * 20 + ocol] = o_mot;
    }
}

// ---------------- launch ----------------
extern "C" void kernel_launch(void* const* d_in, const int* in_sizes, int n_in,
                              void* d_out, int out_size) {
    const float* x  = (const float*)d_in[0];
    const float* Wd = (const float*)d_in[1];
    const float* bd = (const float*)d_in[2];
    const float* Wf = (const float*)d_in[3];
    const float* bf = (const float*)d_in[4];
    const float* Wr = (const float*)d_in[5];
    const float* Wo = (const float*)d_in[6];
    const float* bo = (const float*)d_in[7];
    float* out = (float*)d_out;

    static bool attr_set = false;
    if (!attr_set) {
        cudaFuncSetAttribute(scan_kernel, cudaFuncAttributeMaxDynamicSharedMemorySize,
                             SCAN_FLOATS * 4);
        attr_set = true;
    }

    prep_transpose<<<512, 256>>>(Wf, Wr, Wo);
    prep_wc<<<3 * NUM_INPUT, 256>>>(Wd);
    prep_cvec<<<1, 256>>>(bd, bf);
    gemm_ff0<<<dim3(NUM_HIDDEN / GA_BN, M_ROWS / GA_BM), 256>>>(x);
    scan_kernel<<<64, 512, SCAN_FLOATS * 4>>>(bf, bo, out);
}